// round 17
// baseline (speedup 1.0000x reference)
#include <cuda_runtime.h>

#define J    24
#define TPB  128
#define EPB  64     // elements per block: 2 lanes per element, 16 per warp

__global__ __launch_bounds__(TPB) void fk_kernel(
    const float* __restrict__ angles,   // [B, 24]
    const float* __restrict__ Torg,     // [24, 4, 4]
    const float* __restrict__ axes,     // [24, 3] unit axes
    float* __restrict__ out,            // [B, 75]
    int B)
{
    // Per-joint derived constants: {wx,wy,wz,_, bx,by,bz,_}
    __shared__ __align__(16) float kjc[J][8];
    // Row-major staging: element ce owns s_out[ce*75 .. ce*75+74].
    __shared__ __align__(16) float s_out[EPB * 75];   // 19.2 KB

    const int tid  = threadIdx.x;
    const int warp = tid >> 5;
    const int lane = tid & 31;

    // ---- Warp 0: shuffle-scan of cumulative fixed rotations ----
    // C_j = Q_0 ... Q_j ;  w_j = C_j u_j ;  b_j = C_{j-1} t_j.
    if (warp == 0) {
        float m[9];
        float ax = 0.f, ay = 0.f, az = 0.f;
        float ux = 0.f, uy = 0.f, uz = 0.f;
        m[0]=1.f; m[1]=0.f; m[2]=0.f;
        m[3]=0.f; m[4]=1.f; m[5]=0.f;
        m[6]=0.f; m[7]=0.f; m[8]=1.f;
        if (lane < J) {
            const float* t = Torg + lane * 16;
            m[0]=t[0]; m[1]=t[1]; m[2]=t[2];   ax=t[3];
            m[3]=t[4]; m[4]=t[5]; m[5]=t[6];   ay=t[7];
            m[6]=t[8]; m[7]=t[9]; m[8]=t[10];  az=t[11];
            ux = axes[lane*3+0]; uy = axes[lane*3+1]; uz = axes[lane*3+2];
        }
        #pragma unroll
        for (int d = 1; d < J; d <<= 1) {          // inclusive Kogge-Stone
            float L[9];
            #pragma unroll
            for (int k = 0; k < 9; ++k)
                L[k] = __shfl_up_sync(0xffffffffu, m[k], d);
            if (lane >= d) {
                float n[9];
                #pragma unroll
                for (int r = 0; r < 3; ++r)
                    #pragma unroll
                    for (int c = 0; c < 3; ++c)
                        n[r*3+c] = L[r*3+0]*m[0*3+c] + L[r*3+1]*m[1*3+c]
                                 + L[r*3+2]*m[2*3+c];
                #pragma unroll
                for (int k = 0; k < 9; ++k) m[k] = n[k];
            }
        }
        float E[9];                                 // exclusive prefix
        #pragma unroll
        for (int k = 0; k < 9; ++k)
            E[k] = __shfl_up_sync(0xffffffffu, m[k], 1);
        if (lane == 0) {
            E[0]=1.f; E[1]=0.f; E[2]=0.f;
            E[3]=0.f; E[4]=1.f; E[5]=0.f;
            E[6]=0.f; E[7]=0.f; E[8]=1.f;
        }
        if (lane < J) {
            kjc[lane][0] = m[0]*ux + m[1]*uy + m[2]*uz;   // w = C_j u
            kjc[lane][1] = m[3]*ux + m[4]*uy + m[5]*uz;
            kjc[lane][2] = m[6]*ux + m[7]*uy + m[8]*uz;
            kjc[lane][3] = 0.f;
            kjc[lane][4] = E[0]*ax + E[1]*ay + E[2]*az;   // b = C_{j-1} t
            kjc[lane][5] = E[3]*ax + E[4]*ay + E[5]*az;
            kjc[lane][6] = E[6]*ax + E[7]*ay + E[8]*az;
            kjc[lane][7] = 0.f;
        }
    }

    const int half = lane >> 4;          // 0: joints 0..11, 1: joints 12..23
    const int ew   = lane & 15;          // element index within warp
    const int ce   = warp * 16 + ew;     // element within CTA
    const int base = blockIdx.x * EPB;
    const int e    = base + ce;
    const bool active = (e < B);

    // This half's 12 angles: 3 LDG.128 (offset e*96 + half*48 B, aligned).
    float a[12];
    if (active) {
        const float4* ap =
            reinterpret_cast<const float4*>(angles + (size_t)e * J + half * 12);
        #pragma unroll
        for (int q = 0; q < 3; ++q) {
            float4 v = __ldg(ap + q);
            a[4*q+0] = v.x; a[4*q+1] = v.y; a[4*q+2] = v.z; a[4*q+3] = v.w;
        }
    }

    __syncthreads();   // kjc ready

    // Half-chain state: quaternion P, position p (relative for half==1).
    float Pw = 1.f, Px = 0.f, Py = 0.f, Pz = 0.f;
    float px = 0.f, py = 0.f, pz = 0.f;

    float* so = s_out + ce * 75;
    const float4* kc = reinterpret_cast<const float4*>(kjc);
    const int jb2 = half * 24;            // 2 * (half*12)

    if (active) {
        if (half == 0) { so[0] = 0.f; so[1] = 0.f; so[2] = 0.f; }  // base_pos
        float* soc = so + 3 + 36 * half;  // this half's first staging column

        #pragma unroll
        for (int k = 0; k < 12; ++k) {
            const float4 wv = kc[jb2 + 2*k];       // w_{jb+k}
            const float4 bv = kc[jb2 + 2*k + 1];   // b_{jb+k}

            // p += rot(P, b):  t = qv x b;  p += b + 2*Pw*t + 2*(qv x t)
            const float tx = Py*bv.z - Pz*bv.y;
            const float ty = Pz*bv.x - Px*bv.z;
            const float tz = Px*bv.y - Py*bv.x;
            const float w2 = Pw + Pw;
            const float ox = Py*tz - Pz*ty;
            const float oy = Pz*tx - Px*tz;
            const float oz = Px*ty - Py*tx;
            px += bv.x + w2*tx + 2.f*ox;
            py += bv.y + w2*ty + 2.f*oy;
            pz += bv.z + w2*tz + 2.f*oz;

            soc[3*k + 0] = px;
            soc[3*k + 1] = py;
            soc[3*k + 2] = pz;

            // P <- P (x) (cos h, sin h * w). A needs all 12 (P11 for fixup);
            // B's k=11 update is harmless (result unused) -> uniform code.
            {
                float s, co;
                __sincosf(0.5f * a[k], &s, &co);
                const float qx = s*wv.x, qy = s*wv.y, qz = s*wv.z;
                const float nw = Pw*co - Px*qx - Py*qy - Pz*qz;
                const float nx = Pw*qx + Px*co + Py*qz - Pz*qy;
                const float ny = Pw*qy - Px*qz + Py*co + Pz*qx;
                const float nz = Pw*qz + Px*qy - Py*qx + Pz*co;
                Pw = nw; Px = nx; Py = ny; Pz = nz;
            }
        }
    }

    __syncwarp();   // both halves staged

    // ---- Exchange: broadcast A's (P11, p11) to both lanes of the pair ----
    const unsigned FULL = 0xffffffffu;
    const float Qw = __shfl_sync(FULL, Pw, ew);
    const float Qx = __shfl_sync(FULL, Px, ew);
    const float Qy = __shfl_sync(FULL, Py, ew);
    const float Qz = __shfl_sync(FULL, Pz, ew);
    const float bx = __shfl_sync(FULL, px, ew);
    const float by = __shfl_sync(FULL, py, ew);
    const float bz = __shfl_sync(FULL, pz, ew);

    // ---- Fixup: p_j = p11 + R(P11) * p'_j for joints 12..23 ----
    // Full-warp balanced RMW: A fixes joints 12..17 (cols 39..56),
    // B fixes 18..23 (cols 57..74).
    if (active) {
        const float xx = Qx+Qx, yy = Qy+Qy, zz = Qz+Qz;
        const float r00 = 1.f - (yy*Qy + zz*Qz);
        const float r11 = 1.f - (xx*Qx + zz*Qz);
        const float r22 = 1.f - (xx*Qx + yy*Qy);
        const float xy = xx*Qy, xz = xx*Qz, yz = yy*Qz;
        const float wx = xx*Qw, wy = yy*Qw, wz = zz*Qw;
        const float r01 = xy - wz, r10 = xy + wz;
        const float r02 = xz + wy, r20 = xz - wy;
        const float r12 = yz - wx, r21 = yz + wx;

        float* fx = so + 39 + 18 * half;
        #pragma unroll
        for (int k = 0; k < 6; ++k) {
            const float vx = fx[3*k + 0];
            const float vy = fx[3*k + 1];
            const float vz = fx[3*k + 2];
            fx[3*k + 0] = bx + r00*vx + r01*vy + r02*vz;
            fx[3*k + 1] = by + r10*vx + r11*vy + r12*vz;
            fx[3*k + 2] = bz + r20*vx + r21*vy + r22*vz;
        }
    }

    __syncwarp();   // slab final

    // ---- Warp-private float4 flush of this warp's 16 rows (300 float4) ----
    const int wbase = base + warp * 16;
    if (wbase + 16 <= B) {
        const float4* sv =
            reinterpret_cast<const float4*>(s_out + warp * 16 * 75);
        float4* gv = reinterpret_cast<float4*>(out + (size_t)wbase * 75);
        #pragma unroll
        for (int k = 0; k < 9; ++k)            // 9*32 = 288
            gv[32*k + lane] = sv[32*k + lane];
        if (lane < 12)                          // remaining 12
            gv[288 + lane] = sv[288 + lane];
    } else if (wbase < B) {
        // Generic tail (unused when B % 64 == 0).
        const int cnt = (B - wbase) * 75;
        const float* sf = s_out + warp * 16 * 75;
        float* gf = out + (size_t)wbase * 75;
        for (int i = lane; i < cnt; i += 32) gf[i] = sf[i];
    }
}

extern "C" void kernel_launch(void* const* d_in, const int* in_sizes, int n_in,
                              void* d_out, int out_size) {
    const float* angles = (const float*)d_in[0];   // [B, 24]
    const float* Torg   = (const float*)d_in[1];   // [24, 4, 4]
    const float* axes   = (const float*)d_in[2];   // [24, 3]
    float* out = (float*)d_out;                    // [B, 75]

    const int B = in_sizes[0] / J;
    const int blocks = (B + EPB - 1) / EPB;
    fk_kernel<<<blocks, TPB>>>(angles, Torg, axes, out, B);
}